// round 1
// baseline (speedup 1.0000x reference)
#include <cuda_runtime.h>
#include <math.h>

#define NTOK 32768
#define NM   4
#define IND  204
#define HD   128
#define AD   14
#define KD   32
#define FULL 0xffffffffu

// -------- device scratch (no allocations allowed) --------
__device__ float g_kp[NM * KD];
__device__ int   g_cnt[NM];
__device__ int   g_idx[NM * NTOK];

__device__ __forceinline__ float sigmf(float v) {
    return 1.0f / (1.0f + __expf(-v));
}

// ---------------- kernel 0: mechanism keys projection + counter reset ----------------
__global__ void kp_kernel(const float* __restrict__ mech_keys,
                          const float* __restrict__ wk,
                          const float* __restrict__ bk)
{
    int tid = threadIdx.x;
    if (tid < NM) g_cnt[tid] = 0;
    if (tid < NM * KD) {
        int m = tid >> 5, k = tid & 31;
        float acc = bk[k];
        #pragma unroll
        for (int i = 0; i < KD; i++)
            acc = fmaf(mech_keys[m * KD + i], wk[i * KD + k], acc);
        g_kp[tid] = acc;
    }
}

// ---------------- router: query MLP + attention + gumbel argmax + bucket sort ----------------
__device__ __forceinline__ void layer32(const float* __restrict__ W,
                                        const float* __restrict__ B,
                                        float cur[8], int l, int do_relu)
{
    float nxt[8];
    #pragma unroll
    for (int t = 0; t < 8; t++) nxt[t] = B[l];
    #pragma unroll 4
    for (int i = 0; i < KD; i++) {
        float wv = W[i * KD + l];
        #pragma unroll
        for (int t = 0; t < 8; t++)
            nxt[t] = fmaf(__shfl_sync(FULL, cur[t], i), wv, nxt[t]);
    }
    #pragma unroll
    for (int t = 0; t < 8; t++)
        cur[t] = do_relu ? fmaxf(nxt[t], 0.0f) : nxt[t];
}

__global__ __launch_bounds__(256) void router_kernel(
    const float* __restrict__ hid,
    const float* __restrict__ w1, const float* __restrict__ b1,
    const float* __restrict__ w2, const float* __restrict__ b2,
    const float* __restrict__ w3, const float* __restrict__ b3,
    const float* __restrict__ wq, const float* __restrict__ bq,
    const float* __restrict__ unif)
{
    __shared__ float hs[64 * HD];
    const int tid = threadIdx.x;
    const int t0 = blockIdx.x * 64;
    {
        const float4* src = (const float4*)(hid + (size_t)t0 * HD);
        float4* dst = (float4*)hs;
        for (int e = tid; e < 64 * HD / 4; e += 256) dst[e] = src[e];
    }
    __syncthreads();

    const int w = tid >> 5, l = tid & 31;
    const int wt0 = w * 8;

    // layer 1: [8 tokens] x [H=128 -> K=32], lane = output col
    float cur[8];
    #pragma unroll
    for (int t = 0; t < 8; t++) cur[t] = b1[l];
    #pragma unroll 4
    for (int i = 0; i < HD; i++) {
        float wv = w1[i * KD + l];
        #pragma unroll
        for (int t = 0; t < 8; t++)
            cur[t] = fmaf(hs[(wt0 + t) * HD + i], wv, cur[t]);
    }
    #pragma unroll
    for (int t = 0; t < 8; t++) cur[t] = fmaxf(cur[t], 0.0f);

    layer32(w2, b2, cur, l, 1);  // qh2 = relu(qh@w2+b2)
    layer32(w3, b3, cur, l, 0);  // query = qh2@w3+b3
    layer32(wq, bq, cur, l, 0);  // qp = query@wq+bq

    const float scale = 0.17677669529663687f;  // 1/sqrt(32)
    int mysel = 0;
    int mytok = t0 + wt0 + l;  // lane l < 8 owns token wt0+l

    #pragma unroll
    for (int t = 0; t < 8; t++) {
        float lg[NM];
        #pragma unroll
        for (int m = 0; m < NM; m++) {
            float p = cur[t] * g_kp[m * KD + l];
            #pragma unroll
            for (int off = 16; off > 0; off >>= 1)
                p += __shfl_xor_sync(FULL, p, off);
            lg[m] = p * scale;
        }
        float mx = fmaxf(fmaxf(lg[0], lg[1]), fmaxf(lg[2], lg[3]));
        float es[NM];
        float ssum = 0.0f;
        #pragma unroll
        for (int m = 0; m < NM; m++) { es[m] = expf(lg[m] - mx); ssum += es[m]; }
        float inv = 1.0f / ssum;
        int gt = t0 + wt0 + t;
        float best = -1e30f; int sel = 0;
        #pragma unroll
        for (int m = 0; m < NM; m++) {
            float u = unif[gt * NM + m];
            float gmb = -logf(-logf(u + 1e-10f) + 1e-10f);
            float y = es[m] * inv + gmb;
            if (y > best) { best = y; sel = m; }
        }
        if (l == t) mysel = sel;
    }

    // warp-aggregated bucket insertion (lanes 0..7 own tokens)
    #pragma unroll
    for (int m = 0; m < NM; m++) {
        unsigned mask = __ballot_sync(FULL, (l < 8) && (mysel == m));
        int base = 0;
        if (mask) {
            int leader = __ffs(mask) - 1;
            if (l == leader) base = atomicAdd(&g_cnt[m], __popc(mask));
            base = __shfl_sync(FULL, base, leader);
            if ((l < 8) && (mysel == m)) {
                int pos = base + __popc(mask & ((1u << l) - 1));
                g_idx[m * NTOK + pos] = mytok;
            }
        }
    }
}

// ---------------- main: per-mechanism fused GRU agent on bucketed tokens ----------------
#define SMEM_FLOATS (64 * IND + 3 * 64 * HD)
#define SMEM_BYTES  (SMEM_FLOATS * 4 + 64 * 4)

__global__ __launch_bounds__(256) void mech_kernel(
    const float* __restrict__ x,
    const float* __restrict__ hid,
    const float* __restrict__ fc1w, const float* __restrict__ fc1b,
    const float* __restrict__ wih,  const float* __restrict__ whh,
    const float* __restrict__ bih,  const float* __restrict__ bhh,
    const float* __restrict__ fc2w, const float* __restrict__ fc2b,
    float* __restrict__ out)
{
    extern __shared__ float sm[];
    float* xs   = sm;                // [64][204]
    float* hs   = xs + 64 * IND;     // [64][128]
    float* xas  = hs + 64 * HD;      // [64][128]
    float* hnew = xas + 64 * HD;     // [64][128]
    int*   toks = (int*)(hnew + 64 * HD);  // [64]

    const int m    = blockIdx.x >> 9;
    const int tile = blockIdx.x & 511;
    const int cnt  = g_cnt[m];
    const int start = tile * 64;
    if (start >= cnt) return;
    const int nt  = min(64, cnt - start);
    const int tid = threadIdx.x;

    if (tid < 64) toks[tid] = g_idx[m * NTOK + start + min(tid, nt - 1)];
    __syncthreads();

    // stage h and x tiles
    for (int e = tid; e < 64 * HD / 4; e += 256) {
        int r = e >> 5, c = e & 31;
        ((float4*)hs)[e] = ((const float4*)(hid + (size_t)toks[r] * HD))[c];
    }
    for (int e = tid; e < 64 * IND; e += 256) {
        int r = e / IND, c = e - r * IND;
        xs[e] = x[(size_t)toks[r] * IND + c];
    }
    __syncthreads();

    const int w  = tid >> 5, l = tid & 31;
    const int c0 = l * 4;
    const float* Wf = fc1w + m * IND * HD;
    const float* Wi = wih  + m * HD * 3 * HD;
    const float* Wh = whh  + m * HD * 3 * HD;

    // ---- fc1: xa = relu(x @ fc1_w + b), 8 tokens x 4 cols per thread ----
    {
        float a0[8], a1[8], a2[8], a3[8];
        float4 b4 = *(const float4*)(fc1b + m * HD + c0);
        #pragma unroll
        for (int t = 0; t < 8; t++) { a0[t] = b4.x; a1[t] = b4.y; a2[t] = b4.z; a3[t] = b4.w; }
        const float* xrow = xs + (w * 8) * IND;
        #pragma unroll 2
        for (int i = 0; i < IND; i++) {
            float4 wv = *(const float4*)(Wf + i * HD + c0);
            #pragma unroll
            for (int t = 0; t < 8; t++) {
                float xv = xrow[t * IND + i];
                a0[t] = fmaf(xv, wv.x, a0[t]);
                a1[t] = fmaf(xv, wv.y, a1[t]);
                a2[t] = fmaf(xv, wv.z, a2[t]);
                a3[t] = fmaf(xv, wv.w, a3[t]);
            }
        }
        #pragma unroll
        for (int t = 0; t < 8; t++) {
            float4 v;
            v.x = fmaxf(a0[t], 0.0f); v.y = fmaxf(a1[t], 0.0f);
            v.z = fmaxf(a2[t], 0.0f); v.w = fmaxf(a3[t], 0.0f);
            *(float4*)(xas + (w * 8 + t) * HD + c0) = v;
        }
    }
    __syncthreads();

    // ---- GRU gates, 4 tokens per thread at a time (2 halves) ----
    float* outH = out + (size_t)NTOK * AD;
    float4 brb, bzb, bnb, bhnb;
    {
        float4 bi_r = *(const float4*)(bih + m * 3 * HD + c0);
        float4 bh_r = *(const float4*)(bhh + m * 3 * HD + c0);
        float4 bi_z = *(const float4*)(bih + m * 3 * HD + HD + c0);
        float4 bh_z = *(const float4*)(bhh + m * 3 * HD + HD + c0);
        brb.x = bi_r.x + bh_r.x; brb.y = bi_r.y + bh_r.y; brb.z = bi_r.z + bh_r.z; brb.w = bi_r.w + bh_r.w;
        bzb.x = bi_z.x + bh_z.x; bzb.y = bi_z.y + bh_z.y; bzb.z = bi_z.z + bh_z.z; bzb.w = bi_z.w + bh_z.w;
        bnb  = *(const float4*)(bih + m * 3 * HD + 2 * HD + c0);
        bhnb = *(const float4*)(bhh + m * 3 * HD + 2 * HD + c0);
    }

    #pragma unroll 1
    for (int half = 0; half < 2; half++) {
        const int tb = w * 8 + half * 4;
        float r0[4], r1[4], r2[4], r3[4];
        float z0[4], z1[4], z2[4], z3[4];
        #pragma unroll
        for (int t = 0; t < 4; t++) {
            r0[t] = brb.x; r1[t] = brb.y; r2[t] = brb.z; r3[t] = brb.w;
            z0[t] = bzb.x; z1[t] = bzb.y; z2[t] = bzb.z; z3[t] = bzb.w;
        }
        // gi contribution (A = xa)
        #pragma unroll 4
        for (int i = 0; i < HD; i++) {
            float4 wr = *(const float4*)(Wi + i * 3 * HD + c0);
            float4 wz = *(const float4*)(Wi + i * 3 * HD + HD + c0);
            #pragma unroll
            for (int t = 0; t < 4; t++) {
                float av = xas[(tb + t) * HD + i];
                r0[t] = fmaf(av, wr.x, r0[t]); r1[t] = fmaf(av, wr.y, r1[t]);
                r2[t] = fmaf(av, wr.z, r2[t]); r3[t] = fmaf(av, wr.w, r3[t]);
                z0[t] = fmaf(av, wz.x, z0[t]); z1[t] = fmaf(av, wz.y, z1[t]);
                z2[t] = fmaf(av, wz.z, z2[t]); z3[t] = fmaf(av, wz.w, z3[t]);
            }
        }
        // gh contribution (A = h)
        #pragma unroll 4
        for (int i = 0; i < HD; i++) {
            float4 wr = *(const float4*)(Wh + i * 3 * HD + c0);
            float4 wz = *(const float4*)(Wh + i * 3 * HD + HD + c0);
            #pragma unroll
            for (int t = 0; t < 4; t++) {
                float av = hs[(tb + t) * HD + i];
                r0[t] = fmaf(av, wr.x, r0[t]); r1[t] = fmaf(av, wr.y, r1[t]);
                r2[t] = fmaf(av, wr.z, r2[t]); r3[t] = fmaf(av, wr.w, r3[t]);
                z0[t] = fmaf(av, wz.x, z0[t]); z1[t] = fmaf(av, wz.y, z1[t]);
                z2[t] = fmaf(av, wz.z, z2[t]); z3[t] = fmaf(av, wz.w, z3[t]);
            }
        }
        #pragma unroll
        for (int t = 0; t < 4; t++) {
            r0[t] = sigmf(r0[t]); r1[t] = sigmf(r1[t]); r2[t] = sigmf(r2[t]); r3[t] = sigmf(r3[t]);
            z0[t] = sigmf(z0[t]); z1[t] = sigmf(z1[t]); z2[t] = sigmf(z2[t]); z3[t] = sigmf(z3[t]);
        }

        // n gate: inn (A=xa) and hn (A=h) separately
        float n0[4], n1[4], n2[4], n3[4];
        float q0[4], q1[4], q2[4], q3[4];  // hn accumulators
        #pragma unroll
        for (int t = 0; t < 4; t++) {
            n0[t] = bnb.x;  n1[t] = bnb.y;  n2[t] = bnb.z;  n3[t] = bnb.w;
            q0[t] = bhnb.x; q1[t] = bhnb.y; q2[t] = bhnb.z; q3[t] = bhnb.w;
        }
        #pragma unroll 4
        for (int i = 0; i < HD; i++) {
            float4 wn  = *(const float4*)(Wi + i * 3 * HD + 2 * HD + c0);
            float4 whn = *(const float4*)(Wh + i * 3 * HD + 2 * HD + c0);
            #pragma unroll
            for (int t = 0; t < 4; t++) {
                float xv = xas[(tb + t) * HD + i];
                float hv = hs[(tb + t) * HD + i];
                n0[t] = fmaf(xv, wn.x, n0[t]);  n1[t] = fmaf(xv, wn.y, n1[t]);
                n2[t] = fmaf(xv, wn.z, n2[t]);  n3[t] = fmaf(xv, wn.w, n3[t]);
                q0[t] = fmaf(hv, whn.x, q0[t]); q1[t] = fmaf(hv, whn.y, q1[t]);
                q2[t] = fmaf(hv, whn.z, q2[t]); q3[t] = fmaf(hv, whn.w, q3[t]);
            }
        }
        // combine: h_new = (1-z)*tanh(inn + r*hn) + z*h
        #pragma unroll
        for (int t = 0; t < 4; t++) {
            int j = tb + t;
            float4 hv = *(float4*)(hs + j * HD + c0);
            float g0 = tanhf(n0[t] + r0[t] * q0[t]);
            float g1 = tanhf(n1[t] + r1[t] * q1[t]);
            float g2 = tanhf(n2[t] + r2[t] * q2[t]);
            float g3 = tanhf(n3[t] + r3[t] * q3[t]);
            float4 o;
            o.x = (1.0f - z0[t]) * g0 + z0[t] * hv.x;
            o.y = (1.0f - z1[t]) * g1 + z1[t] * hv.y;
            o.z = (1.0f - z2[t]) * g2 + z2[t] * hv.z;
            o.w = (1.0f - z3[t]) * g3 + z3[t] * hv.w;
            *(float4*)(hnew + j * HD + c0) = o;
            if (j < nt)
                *(float4*)(outH + (size_t)toks[j] * HD + c0) = o;
        }
    }
    __syncthreads();

    // ---- fc2: q = h_new @ fc2_w + fc2_b, write qs ----
    for (int oi = tid; oi < 64 * AD; oi += 256) {
        int t = oi / AD, a = oi - t * AD;
        if (t < nt) {
            float acc = fc2b[m * AD + a];
            const float* wp = fc2w + m * HD * AD + a;
            const float* hp = hnew + t * HD;
            #pragma unroll 4
            for (int i = 0; i < HD; i++)
                acc = fmaf(hp[i], __ldg(wp + i * AD), acc);
            out[(size_t)toks[t] * AD + a] = acc;
        }
    }
}

// ---------------- launch ----------------
extern "C" void kernel_launch(void* const* d_in, const int* in_sizes, int n_in,
                              void* d_out, int out_size)
{
    const float* x    = (const float*)d_in[0];
    const float* hid  = (const float*)d_in[1];
    const float* fc1w = (const float*)d_in[2];
    const float* fc1b = (const float*)d_in[3];
    const float* wih  = (const float*)d_in[4];
    const float* whh  = (const float*)d_in[5];
    const float* bih  = (const float*)d_in[6];
    const float* bhh  = (const float*)d_in[7];
    const float* fc2w = (const float*)d_in[8];
    const float* fc2b = (const float*)d_in[9];
    const float* w1   = (const float*)d_in[10];
    const float* b1   = (const float*)d_in[11];
    const float* w2   = (const float*)d_in[12];
    const float* b2   = (const float*)d_in[13];
    const float* w3   = (const float*)d_in[14];
    const float* b3   = (const float*)d_in[15];
    const float* mk   = (const float*)d_in[16];
    const float* wq   = (const float*)d_in[17];
    const float* bq   = (const float*)d_in[18];
    const float* wk   = (const float*)d_in[19];
    const float* bk   = (const float*)d_in[20];
    const float* unif = (const float*)d_in[21];
    float* out = (float*)d_out;

    cudaFuncSetAttribute(mech_kernel, cudaFuncAttributeMaxDynamicSharedMemorySize, SMEM_BYTES);

    kp_kernel<<<1, 128>>>(mk, wk, bk);
    router_kernel<<<NTOK / 64, 256>>>(hid, w1, b1, w2, b2, w3, b3, wq, bq, unif);
    mech_kernel<<<NM * 512, 256, SMEM_BYTES>>>(x, hid, fc1w, fc1b, wih, whh,
                                               bih, bhh, fc2w, fc2b, out);
}

// round 3
// speedup vs baseline: 1.3834x; 1.3834x over previous
#include <cuda_runtime.h>
#include <math.h>

#define NTOK 32768
#define NM   4
#define IND  204
#define HD   128
#define AD   14
#define KD   32
#define TILE 32
#define FULL 0xffffffffu

typedef unsigned long long u64;

// -------- device scratch (no allocations allowed) --------
__device__ float g_kp[NM * KD];
__device__ int   g_cnt[NM];
__device__ int   g_ticket;
__device__ int   g_idx[NM * NTOK];

__device__ __forceinline__ float sigmf(float v) {
    return 1.0f / (1.0f + __expf(-v));
}

// ---- packed f32x2 helpers (Blackwell FFMA2 path) ----
__device__ __forceinline__ u64 pk2d(float v) {            // duplicate
    u64 r; asm("mov.b64 %0,{%1,%1};" : "=l"(r) : "f"(v)); return r;
}
__device__ __forceinline__ u64 pk2(float a, float b) {
    u64 r; asm("mov.b64 %0,{%1,%2};" : "=l"(r) : "f"(a), "f"(b)); return r;
}
__device__ __forceinline__ void fma2(u64& d, u64 a, u64 b) {
    asm("fma.rn.f32x2 %0,%1,%2,%0;" : "+l"(d) : "l"(a), "l"(b));
}
__device__ __forceinline__ float2 unpk(u64 v) {
    float2 f; asm("mov.b64 {%0,%1},%2;" : "=f"(f.x), "=f"(f.y) : "l"(v)); return f;
}

// ---------------- kernel 0: mechanism keys projection + counter reset ----------------
__global__ void kp_kernel(const float* __restrict__ mech_keys,
                          const float* __restrict__ wk,
                          const float* __restrict__ bk)
{
    int tid = threadIdx.x;
    if (tid == 0) g_ticket = 0;
    if (tid < NM) g_cnt[tid] = 0;
    if (tid < NM * KD) {
        int m = tid >> 5, k = tid & 31;
        float acc = bk[k];
        #pragma unroll
        for (int i = 0; i < KD; i++)
            acc = fmaf(mech_keys[m * KD + i], wk[i * KD + k], acc);
        g_kp[tid] = acc;
    }
}

// ---------------- router: query MLP + attention + gumbel argmax + bucket sort ----------------
__device__ __forceinline__ void layer32(const float* __restrict__ W,
                                        const float* __restrict__ B,
                                        float cur[8], int l, int do_relu)
{
    float nxt[8];
    #pragma unroll
    for (int t = 0; t < 8; t++) nxt[t] = B[l];
    #pragma unroll 4
    for (int i = 0; i < KD; i++) {
        float wv = W[i * KD + l];
        #pragma unroll
        for (int t = 0; t < 8; t++)
            nxt[t] = fmaf(__shfl_sync(FULL, cur[t], i), wv, nxt[t]);
    }
    #pragma unroll
    for (int t = 0; t < 8; t++)
        cur[t] = do_relu ? fmaxf(nxt[t], 0.0f) : nxt[t];
}

__global__ __launch_bounds__(256) void router_kernel(
    const float* __restrict__ hid,
    const float* __restrict__ w1, const float* __restrict__ b1,
    const float* __restrict__ w2, const float* __restrict__ b2,
    const float* __restrict__ w3, const float* __restrict__ b3,
    const float* __restrict__ wq, const float* __restrict__ bq,
    const float* __restrict__ unif)
{
    __shared__ float hs[64 * HD];
    const int tid = threadIdx.x;
    const int t0 = blockIdx.x * 64;
    {
        const float4* src = (const float4*)(hid + (size_t)t0 * HD);
        float4* dst = (float4*)hs;
        for (int e = tid; e < 64 * HD / 4; e += 256) dst[e] = src[e];
    }
    __syncthreads();

    const int w = tid >> 5, l = tid & 31;
    const int wt0 = w * 8;

    float cur[8];
    #pragma unroll
    for (int t = 0; t < 8; t++) cur[t] = b1[l];
    #pragma unroll 4
    for (int i = 0; i < HD; i++) {
        float wv = w1[i * KD + l];
        #pragma unroll
        for (int t = 0; t < 8; t++)
            cur[t] = fmaf(hs[(wt0 + t) * HD + i], wv, cur[t]);
    }
    #pragma unroll
    for (int t = 0; t < 8; t++) cur[t] = fmaxf(cur[t], 0.0f);

    layer32(w2, b2, cur, l, 1);
    layer32(w3, b3, cur, l, 0);
    layer32(wq, bq, cur, l, 0);

    const float scale = 0.17677669529663687f;  // 1/sqrt(32)
    int mysel = 0;
    int mytok = t0 + wt0 + l;

    #pragma unroll
    for (int t = 0; t < 8; t++) {
        float lg[NM];
        #pragma unroll
        for (int m = 0; m < NM; m++) {
            float p = cur[t] * g_kp[m * KD + l];
            #pragma unroll
            for (int off = 16; off > 0; off >>= 1)
                p += __shfl_xor_sync(FULL, p, off);
            lg[m] = p * scale;
        }
        float mx = fmaxf(fmaxf(lg[0], lg[1]), fmaxf(lg[2], lg[3]));
        float es[NM];
        float ssum = 0.0f;
        #pragma unroll
        for (int m = 0; m < NM; m++) { es[m] = expf(lg[m] - mx); ssum += es[m]; }
        float inv = 1.0f / ssum;
        int gt = t0 + wt0 + t;
        float best = -1e30f; int sel = 0;
        #pragma unroll
        for (int m = 0; m < NM; m++) {
            float u = unif[gt * NM + m];
            float gmb = -logf(-logf(u + 1e-10f) + 1e-10f);
            float y = es[m] * inv + gmb;
            if (y > best) { best = y; sel = m; }
        }
        if (l == t) mysel = sel;
    }

    #pragma unroll
    for (int m = 0; m < NM; m++) {
        unsigned mask = __ballot_sync(FULL, (l < 8) && (mysel == m));
        int base = 0;
        if (mask) {
            int leader = __ffs(mask) - 1;
            if (l == leader) base = atomicAdd(&g_cnt[m], __popc(mask));
            base = __shfl_sync(FULL, base, leader);
            if ((l < 8) && (mysel == m)) {
                int pos = base + __popc(mask & ((1u << l) - 1));
                g_idx[m * NTOK + pos] = mytok;
            }
        }
    }
}

// ---------------- main: persistent per-mechanism fused GRU agent, f32x2 math ----------------
// smem: xs [32*204] (reused as hnew [32*128]), hs [32*128], xas [32*128], toks, ticket
#define SMEM_FLOATS (TILE * IND + 2 * TILE * HD)
#define SMEM_BYTES  (SMEM_FLOATS * 4 + TILE * 4 + 16)

__global__ __launch_bounds__(128, 2) void mech_kernel(
    const float* __restrict__ x,
    const float* __restrict__ hid,
    const float* __restrict__ fc1w, const float* __restrict__ fc1b,
    const float* __restrict__ wih,  const float* __restrict__ whh,
    const float* __restrict__ bih,  const float* __restrict__ bhh,
    const float* __restrict__ fc2w, const float* __restrict__ fc2b,
    float* __restrict__ out)
{
    extern __shared__ float sm[];
    float* xs   = sm;                       // [32][204], aliased by hnew
    float* hs   = xs + TILE * IND;          // [32][128]
    float* xas  = hs + TILE * HD;           // [32][128]
    float* hnew = xs;                       // alias (xs dead after fc1)
    int*   toks = (int*)(xas + TILE * HD);  // [32]
    int*   s_tk = toks + TILE;

    const int tid = threadIdx.x;
    const int w   = tid >> 5, l = tid & 31;
    const int c0  = l * 4;
    const int tw0 = w * 8;                  // warp's first token row
    float* outH = out + (size_t)NTOK * AD;

    // per-mechanism tile prefix
    int cc[NM], pre[NM];
    int total = 0;
    #pragma unroll
    for (int m = 0; m < NM; m++) {
        cc[m] = g_cnt[m];
        total += (cc[m] + TILE - 1) / TILE;
        pre[m] = total;
    }
    if (total <= 0) return;

    for (;;) {
        if (tid == 0) *s_tk = atomicAdd(&g_ticket, 1);
        __syncthreads();
        const int tk = *s_tk;
        if (tk >= total) break;

        int m = 0;
        #pragma unroll
        for (int j = 0; j < NM - 1; j++) if (tk >= pre[j]) m = j + 1;
        const int prev = m ? pre[m - 1] : 0;
        const int t0   = (tk - prev) * TILE;
        const int nt   = min(TILE, cc[m] - t0);

        if (tid < TILE) toks[tid] = g_idx[m * NTOK + t0 + min(tid, nt - 1)];
        __syncthreads();

        // stage x and h tiles
        for (int e = tid; e < TILE * (IND / 4); e += 128) {
            int r = e / (IND / 4), c = e - r * (IND / 4);
            ((float4*)(xs + r * IND))[c] = ((const float4*)(x + (size_t)toks[r] * IND))[c];
        }
        for (int e = tid; e < TILE * (HD / 4); e += 128) {
            int r = e >> 5, c = e & 31;
            ((float4*)hs)[e] = ((const float4*)(hid + (size_t)toks[r] * HD))[c];
        }
        __syncthreads();

        const float* Wf = fc1w + m * IND * HD;
        const float* Wi = wih  + m * HD * 3 * HD;
        const float* Wh = whh  + m * HD * 3 * HD;

        // ---- fc1: xa = relu(x @ W + b); 8 tok x 4 cols per thread, f32x2 ----
        {
            u64 a[8][2];
            float4 b4 = *(const float4*)(fc1b + m * HD + c0);
            u64 bA = pk2(b4.x, b4.y), bB = pk2(b4.z, b4.w);
            #pragma unroll
            for (int t = 0; t < 8; t++) { a[t][0] = bA; a[t][1] = bB; }
            const float* xrow = xs + tw0 * IND;
            #pragma unroll 4
            for (int i = 0; i < IND; i++) {
                ulonglong2 wv = *(const ulonglong2*)(Wf + i * HD + c0);
                #pragma unroll
                for (int t = 0; t < 8; t++) {
                    u64 xp = pk2d(xrow[t * IND + i]);
                    fma2(a[t][0], xp, wv.x);
                    fma2(a[t][1], xp, wv.y);
                }
            }
            #pragma unroll
            for (int t = 0; t < 8; t++) {
                float2 v0 = unpk(a[t][0]), v1 = unpk(a[t][1]);
                float4 v;
                v.x = fmaxf(v0.x, 0.0f); v.y = fmaxf(v0.y, 0.0f);
                v.z = fmaxf(v1.x, 0.0f); v.w = fmaxf(v1.y, 0.0f);
                *(float4*)(xas + (tw0 + t) * HD + c0) = v;
            }
        }
        // no sync: xas rows are produced & consumed by the same warp

        // ---- r/z gates: 8 tok x (4r + 4z) cols, passes over Wi then Wh ----
        float rs[8][4], zs[8][4];
        {
            u64 r_[8][2], z_[8][2];
            {
                float4 bi_r = *(const float4*)(bih + m * 3 * HD + c0);
                float4 bh_r = *(const float4*)(bhh + m * 3 * HD + c0);
                float4 bi_z = *(const float4*)(bih + m * 3 * HD + HD + c0);
                float4 bh_z = *(const float4*)(bhh + m * 3 * HD + HD + c0);
                u64 rA = pk2(bi_r.x + bh_r.x, bi_r.y + bh_r.y);
                u64 rB = pk2(bi_r.z + bh_r.z, bi_r.w + bh_r.w);
                u64 zA = pk2(bi_z.x + bh_z.x, bi_z.y + bh_z.y);
                u64 zB = pk2(bi_z.z + bh_z.z, bi_z.w + bh_z.w);
                #pragma unroll
                for (int t = 0; t < 8; t++) {
                    r_[t][0] = rA; r_[t][1] = rB;
                    z_[t][0] = zA; z_[t][1] = zB;
                }
            }
            #pragma unroll 2
            for (int i = 0; i < HD; i++) {
                ulonglong2 wr = *(const ulonglong2*)(Wi + i * 3 * HD + c0);
                ulonglong2 wz = *(const ulonglong2*)(Wi + i * 3 * HD + HD + c0);
                #pragma unroll
                for (int t = 0; t < 8; t++) {
                    u64 av = pk2d(xas[(tw0 + t) * HD + i]);
                    fma2(r_[t][0], av, wr.x); fma2(r_[t][1], av, wr.y);
                    fma2(z_[t][0], av, wz.x); fma2(z_[t][1], av, wz.y);
                }
            }
            #pragma unroll 2
            for (int i = 0; i < HD; i++) {
                ulonglong2 wr = *(const ulonglong2*)(Wh + i * 3 * HD + c0);
                ulonglong2 wz = *(const ulonglong2*)(Wh + i * 3 * HD + HD + c0);
                #pragma unroll
                for (int t = 0; t < 8; t++) {
                    u64 av = pk2d(hs[(tw0 + t) * HD + i]);
                    fma2(r_[t][0], av, wr.x); fma2(r_[t][1], av, wr.y);
                    fma2(z_[t][0], av, wz.x); fma2(z_[t][1], av, wz.y);
                }
            }
            #pragma unroll
            for (int t = 0; t < 8; t++) {
                float2 a0 = unpk(r_[t][0]), a1 = unpk(r_[t][1]);
                float2 b0 = unpk(z_[t][0]), b1 = unpk(z_[t][1]);
                rs[t][0] = sigmf(a0.x); rs[t][1] = sigmf(a0.y);
                rs[t][2] = sigmf(a1.x); rs[t][3] = sigmf(a1.y);
                zs[t][0] = sigmf(b0.x); zs[t][1] = sigmf(b0.y);
                zs[t][2] = sigmf(b1.x); zs[t][3] = sigmf(b1.y);
            }
        }

        // ---- n gate: inn (xa @ Wi_n) and hn (h @ Wh_n) ----
        {
            u64 n_[8][2], q_[8][2];
            {
                float4 bn  = *(const float4*)(bih + m * 3 * HD + 2 * HD + c0);
                float4 bhn = *(const float4*)(bhh + m * 3 * HD + 2 * HD + c0);
                u64 nA = pk2(bn.x, bn.y),  nB = pk2(bn.z, bn.w);
                u64 qA = pk2(bhn.x, bhn.y), qB = pk2(bhn.z, bhn.w);
                #pragma unroll
                for (int t = 0; t < 8; t++) {
                    n_[t][0] = nA; n_[t][1] = nB;
                    q_[t][0] = qA; q_[t][1] = qB;
                }
            }
            #pragma unroll 2
            for (int i = 0; i < HD; i++) {
                ulonglong2 wn  = *(const ulonglong2*)(Wi + i * 3 * HD + 2 * HD + c0);
                ulonglong2 whn = *(const ulonglong2*)(Wh + i * 3 * HD + 2 * HD + c0);
                #pragma unroll
                for (int t = 0; t < 8; t++) {
                    u64 xv = pk2d(xas[(tw0 + t) * HD + i]);
                    u64 hv = pk2d(hs[(tw0 + t) * HD + i]);
                    fma2(n_[t][0], xv, wn.x);  fma2(n_[t][1], xv, wn.y);
                    fma2(q_[t][0], hv, whn.x); fma2(q_[t][1], hv, whn.y);
                }
            }
            // combine: h' = (1-z)*tanh(inn + r*hn) + z*h
            #pragma unroll
            for (int t = 0; t < 8; t++) {
                int j = tw0 + t;
                float2 n0 = unpk(n_[t][0]), n1 = unpk(n_[t][1]);
                float2 q0 = unpk(q_[t][0]), q1 = unpk(q_[t][1]);
                float4 hv = *(float4*)(hs + j * HD + c0);
                float g0 = tanhf(n0.x + rs[t][0] * q0.x);
                float g1 = tanhf(n0.y + rs[t][1] * q0.y);
                float g2 = tanhf(n1.x + rs[t][2] * q1.x);
                float g3 = tanhf(n1.y + rs[t][3] * q1.y);
                float4 o;
                o.x = (1.0f - zs[t][0]) * g0 + zs[t][0] * hv.x;
                o.y = (1.0f - zs[t][1]) * g1 + zs[t][1] * hv.y;
                o.z = (1.0f - zs[t][2]) * g2 + zs[t][2] * hv.z;
                o.w = (1.0f - zs[t][3]) * g3 + zs[t][3] * hv.w;
                *(float4*)(hnew + j * HD + c0) = o;
                if (j < nt)
                    *(float4*)(outH + (size_t)toks[j] * HD + c0) = o;
            }
        }
        __syncthreads();   // hnew visible to all threads for fc2

        // ---- fc2: q = h_new @ fc2_w + fc2_b ----
        for (int oi = tid; oi < TILE * AD; oi += 128) {
            int t = oi / AD, a = oi - t * AD;
            if (t < nt) {
                float acc = fc2b[m * AD + a];
                const float* wp = fc2w + m * HD * AD + a;
                const float* hp = hnew + t * HD;
                #pragma unroll 4
                for (int i = 0; i < HD; i++)
                    acc = fmaf(hp[i], __ldg(wp + i * AD), acc);
                out[(size_t)toks[t] * AD + a] = acc;
            }
        }
        // ticket-broadcast sync at loop head separates fc2 reads from restaging
    }
}

// ---------------- launch ----------------
extern "C" void kernel_launch(void* const* d_in, const int* in_sizes, int n_in,
                              void* d_out, int out_size)
{
    const float* x    = (const float*)d_in[0];
    const float* hid  = (const float*)d_in[1];
    const float* fc1w = (const float*)d_in[2];
    const float* fc1b = (const float*)d_in[3];
    const float* wih  = (const float*)d_in[4];
    const float* whh  = (const float*)d_in[5];
    const float* bih  = (const float*)d_in[6];
    const float* bhh  = (const float*)d_in[7];
    const float* fc2w = (const float*)d_in[8];
    const float* fc2b = (const float*)d_in[9];
    const float* w1   = (const float*)d_in[10];
    const float* b1   = (const float*)d_in[11];
    const float* w2   = (const float*)d_in[12];
    const float* b2   = (const float*)d_in[13];
    const float* w3   = (const float*)d_in[14];
    const float* b3   = (const float*)d_in[15];
    const float* mk   = (const float*)d_in[16];
    const float* wq   = (const float*)d_in[17];
    const float* bq   = (const float*)d_in[18];
    const float* wk   = (const float*)d_in[19];
    const float* bk   = (const float*)d_in[20];
    const float* unif = (const float*)d_in[21];
    float* out = (float*)d_out;

    cudaFuncSetAttribute(mech_kernel, cudaFuncAttributeMaxDynamicSharedMemorySize, SMEM_BYTES);

    kp_kernel<<<1, 128>>>(mk, wk, bk);
    router_kernel<<<NTOK / 64, 256>>>(hid, w1, b1, w2, b2, w3, b3, wq, bq, unif);
    mech_kernel<<<320, 128, SMEM_BYTES>>>(x, hid, fc1w, fc1b, wih, whh,
                                          bih, bhh, fc2w, fc2b, out);
}